// round 7
// baseline (speedup 1.0000x reference)
#include <cuda_runtime.h>
#include <cuda_bf16.h>
#include <cstdint>

// Causal attention, B=16, N=2048, D=256, fp32 I/O.
// FlashAttention-2, tf32 mma.sync (m16n8k8), XOR-swizzled fragment smem layouts.
// R6: pair-packed K/V fragment blocks -> all B-operand fetches are LDS.128
//     feeding two mma k-steps (halves LDS instruction count in hot loops).

#define BQ    128
#define BK    32
#define NWARP 8
#define NTHR  256
#define BATCH 16
#define SEQ   2048
#define DIM   256
#define NTQ   (SEQ / BQ)
#define QK_SCALE 0.0625f
#define LOG2E 1.4426950408889634f

// smem (uint32 words)
#define QS_OFF 0        // Q A-frags: 8 wrb * 32 c * 128 words          (131072 B)
#define KS_OFF 32768    // K B-frag pairs: 4 nt * 16 cp * 128 words     (32768 B)
#define VS_OFF 40960    // V B-frag pairs: 32 dt * 2 kcp * 128 words    (32768 B)
#define PS_OFF 49152    // P A-frags: 8 warp * 4 kc * 128 words         (16384 B)
#define PAD_OFF 53248
#define SMEM_WORDS (53248 + 32)
#define SMEM_BYTES (SMEM_WORDS * 4)

__device__ __forceinline__ uint32_t f2tf32(float x) {
    uint32_t u;
    asm("cvt.rna.tf32.f32 %0, %1;" : "=r"(u) : "f"(x));
    return u;
}

__device__ __forceinline__ float ex2(float x) {
    float r;
    asm("ex2.approx.ftz.f32 %0, %1;" : "=f"(r) : "f"(x));
    return r;
}

__device__ __forceinline__ void mma8(float* d, const uint32_t* a, const uint32_t* b) {
    asm volatile(
        "mma.sync.aligned.m16n8k8.row.col.f32.tf32.tf32.f32 "
        "{%0,%1,%2,%3},{%4,%5,%6,%7},{%8,%9},{%0,%1,%2,%3};\n"
        : "+f"(d[0]), "+f"(d[1]), "+f"(d[2]), "+f"(d[3])
        : "r"(a[0]), "r"(a[1]), "r"(a[2]), "r"(a[3]), "r"(b[0]), "r"(b[1]));
}

__global__ void __launch_bounds__(NTHR, 1)
fa_tf32_kernel(const float* __restrict__ Q, const float* __restrict__ K,
               const float* __restrict__ V, const int* __restrict__ PM,
               float* __restrict__ O)
{
    extern __shared__ uint32_t sm[];
    uint32_t* Qs = sm + QS_OFF;
    uint32_t* Ks = sm + KS_OFF;
    uint32_t* Vs = sm + VS_OFF;
    uint32_t* Ps = sm + PS_OFF;
    int* pads    = (int*)(sm + PAD_OFF);

    const int tid  = threadIdx.x;
    const int warp = tid >> 5;
    const int lane = tid & 31;
    const int g    = lane >> 2;
    const int t    = lane & 3;

    const int b  = blockIdx.x & (BATCH - 1);
    const int qt = NTQ - 1 - (blockIdx.x >> 4);
    const int q0 = qt * BQ;

    // ---- stage Q tile into A-fragment layout (pre-scaled, tf32, XOR-swizzled) ----
    const float* Qg = Q + ((size_t)b * SEQ + q0) * DIM;
    for (int i = tid; i < BQ * DIM / 4; i += NTHR) {
        int idx = i * 4;
        float4 v = *reinterpret_cast<const float4*>(Qg + idx);
        int r = idx >> 8;
        int d = idx & 255;
        float vv[4] = {v.x, v.y, v.z, v.w};
        #pragma unroll
        for (int e = 0; e < 4; e++) {
            int dd = d + e;
            int wrb   = r >> 4;
            int c     = dd >> 3;
            int lane2 = ((r & 7) << 2) | (dd & 3);
            int a     = ((r >> 3) & 1) | (((dd >> 2) & 1) << 1);
            uint32_t off = (uint32_t)(((lane2 << 2) | a) ^ ((c & 7) << 2));
            Qs[(uint32_t)(wrb * 32 + c) * 128 + off] = f2tf32(vv[e] * QK_SCALE);
        }
    }

    // ---- accumulators ----
    float o[32][4];
    #pragma unroll
    for (int i = 0; i < 32; i++) { o[i][0] = 0.f; o[i][1] = 0.f; o[i][2] = 0.f; o[i][3] = 0.f; }
    float m0 = -1e30f, m1 = -1e30f, l0 = 0.f, l1 = 0.f;

    const int wrow = q0 + warp * 16;
    const int KT   = (q0 + BQ) / BK;
    const float* Kg0 = K + (size_t)b * SEQ * DIM;
    const float* Vg0 = V + (size_t)b * SEQ * DIM;

    for (int kt = 0; kt < KT; kt++) {
        const int k0 = kt * BK;

        __syncthreads();
        // ---- stage K,V tiles into pair-packed XOR-swizzled B-fragment layouts ----
        const float* Kg = Kg0 + (size_t)k0 * DIM;
        const float* Vg = Vg0 + (size_t)k0 * DIM;
        for (int i = tid; i < BK * DIM / 4; i += NTHR) {
            int idx = i * 4;
            float4 kv = *reinterpret_cast<const float4*>(Kg + idx);
            float4 vv = *reinterpret_cast<const float4*>(Vg + idx);
            int r = idx >> 8;
            int d = idx & 255;
            float ka[4] = {kv.x, kv.y, kv.z, kv.w};
            float va[4] = {vv.x, vv.y, vv.z, vv.w};
            #pragma unroll
            for (int e = 0; e < 4; e++) {
                int dd = d + e;
                // K: block (nt=r/8, cp=dd/16), 128 words
                //    word = lane2*4 + (c&1)*2 + bi, XOR (cp&7)<<2
                {
                    int nt    = r >> 3;
                    int cp    = dd >> 4;
                    int lane2 = ((r & 7) << 2) | (dd & 3);
                    int sub   = (((dd >> 3) & 1) << 1) | ((dd >> 2) & 1);
                    uint32_t off = (uint32_t)(((lane2 << 2) | sub) ^ ((cp & 7) << 2));
                    Ks[(uint32_t)(nt * 16 + cp) * 128 + off] = f2tf32(ka[e]);
                }
                // V: block (dt=dd/8, kcp=r/16), 128 words
                //    word = lane2*4 + (kc&1)*2 + bi, XOR (dt&7)<<2
                {
                    int dt    = dd >> 3;
                    int kcp   = r >> 4;
                    int lane2 = ((dd & 7) << 2) | (r & 3);
                    int sub   = (((r >> 3) & 1) << 1) | ((r >> 2) & 1);
                    uint32_t off = (uint32_t)(((lane2 << 2) | sub) ^ ((dt & 7) << 2));
                    Vs[(uint32_t)(dt * 2 + kcp) * 128 + off] = f2tf32(va[e]);
                }
            }
        }
        if (tid < BK) pads[tid] = PM[(size_t)b * SEQ + k0 + tid];
        __syncthreads();

        if (k0 > wrow + 15) continue;

        // ---- S = (Q*scale) K^T : 16 cp-steps, each 2 k8 steps ----
        float s[4][4];
        #pragma unroll
        for (int nt = 0; nt < 4; nt++) { s[nt][0] = s[nt][1] = s[nt][2] = s[nt][3] = 0.f; }
        #pragma unroll
        for (int cp = 0; cp < 16; cp++) {
            const int c0 = 2 * cp, c1 = 2 * cp + 1;
            uint4 qa0 = *reinterpret_cast<const uint4*>(
                &Qs[(uint32_t)(warp * 32 + c0) * 128 + (uint32_t)((lane << 2) ^ ((c0 & 7) << 2))]);
            uint4 qa1 = *reinterpret_cast<const uint4*>(
                &Qs[(uint32_t)(warp * 32 + c1) * 128 + (uint32_t)((lane << 2) ^ ((c1 & 7) << 2))]);
            uint32_t A0[4] = {qa0.x, qa0.y, qa0.z, qa0.w};
            uint32_t A1[4] = {qa1.x, qa1.y, qa1.z, qa1.w};
            const uint32_t koff = (uint32_t)((lane << 2) ^ ((cp & 7) << 2));
            #pragma unroll
            for (int nt = 0; nt < 4; nt++) {
                uint4 kb = *reinterpret_cast<const uint4*>(&Ks[(uint32_t)(nt * 16 + cp) * 128 + koff]);
                uint32_t B0[2] = {kb.x, kb.y};
                uint32_t B1[2] = {kb.z, kb.w};
                mma8(s[nt], A0, B0);
                mma8(s[nt], A1, B1);
            }
        }

        // ---- mask + online softmax ----
        const int row0 = wrow + g;
        const int row1 = row0 + 8;
        float rm0 = -1e30f, rm1 = -1e30f;
        #pragma unroll
        for (int nt = 0; nt < 4; nt++) {
            int j0 = k0 + nt * 8 + 2 * t;
            int j1 = j0 + 1;
            bool ok0 = (pads[j0 - k0] != 0);
            bool ok1 = (pads[j1 - k0] != 0);
            if (!(ok0 && j0 <= row0)) s[nt][0] = -1e30f;
            if (!(ok1 && j1 <= row0)) s[nt][1] = -1e30f;
            if (!(ok0 && j0 <= row1)) s[nt][2] = -1e30f;
            if (!(ok1 && j1 <= row1)) s[nt][3] = -1e30f;
            rm0 = fmaxf(rm0, fmaxf(s[nt][0], s[nt][1]));
            rm1 = fmaxf(rm1, fmaxf(s[nt][2], s[nt][3]));
        }
        rm0 = fmaxf(rm0, __shfl_xor_sync(0xffffffffu, rm0, 1));
        rm0 = fmaxf(rm0, __shfl_xor_sync(0xffffffffu, rm0, 2));
        rm1 = fmaxf(rm1, __shfl_xor_sync(0xffffffffu, rm1, 1));
        rm1 = fmaxf(rm1, __shfl_xor_sync(0xffffffffu, rm1, 2));

        float mn0 = fmaxf(m0, rm0), mn1 = fmaxf(m1, rm1);
        float sc0 = ex2((m0 - mn0) * LOG2E);
        float sc1 = ex2((m1 - mn1) * LOG2E);
        m0 = mn0; m1 = mn1;
        l0 *= sc0; l1 *= sc1;
        #pragma unroll
        for (int dt = 0; dt < 32; dt++) {
            o[dt][0] *= sc0; o[dt][1] *= sc0;
            o[dt][2] *= sc1; o[dt][3] *= sc1;
        }

        __syncwarp();
        float ls0 = 0.f, ls1 = 0.f;
        #pragma unroll
        for (int nt = 0; nt < 4; nt++) {
            float p0 = ex2((s[nt][0] - mn0) * LOG2E);
            float p1 = ex2((s[nt][1] - mn0) * LOG2E);
            float p2 = ex2((s[nt][2] - mn1) * LOG2E);
            float p3 = ex2((s[nt][3] - mn1) * LOG2E);
            ls0 += p0 + p1;
            ls1 += p2 + p3;
            int base = (warp * 4 + nt) * 128;
            int t20 = (2 * t) & 3,     hi0 = (2 * t) >> 2;
            int t21 = (2 * t + 1) & 3, hi1 = (2 * t + 1) >> 2;
            Ps[base + (g * 4 + t20) * 4 + 0 + 2 * hi0] = f2tf32(p0);
            Ps[base + (g * 4 + t21) * 4 + 0 + 2 * hi1] = f2tf32(p1);
            Ps[base + (g * 4 + t20) * 4 + 1 + 2 * hi0] = f2tf32(p2);
            Ps[base + (g * 4 + t21) * 4 + 1 + 2 * hi1] = f2tf32(p3);
        }
        l0 += ls0; l1 += ls1;
        __syncwarp();

        // ---- O += P V : 2 kcp-steps, V pair per LDS.128 ----
        #pragma unroll
        for (int kcp = 0; kcp < 2; kcp++) {
            uint4 pa0 = *reinterpret_cast<const uint4*>(&Ps[(warp * 4 + 2 * kcp)     * 128 + lane * 4]);
            uint4 pa1 = *reinterpret_cast<const uint4*>(&Ps[(warp * 4 + 2 * kcp + 1) * 128 + lane * 4]);
            uint32_t A0[4] = {pa0.x, pa0.y, pa0.z, pa0.w};
            uint32_t A1[4] = {pa1.x, pa1.y, pa1.z, pa1.w};
            #pragma unroll
            for (int dt = 0; dt < 32; dt++) {
                uint4 vb = *reinterpret_cast<const uint4*>(
                    &Vs[(uint32_t)(dt * 2 + kcp) * 128 + (uint32_t)((lane << 2) ^ ((dt & 7) << 2))]);
                uint32_t B0[2] = {vb.x, vb.y};
                uint32_t B1[2] = {vb.z, vb.w};
                mma8(o[dt], A0, B0);
                mma8(o[dt], A1, B1);
            }
        }
    }

    // ---- epilogue ----
    l0 += __shfl_xor_sync(0xffffffffu, l0, 1);
    l0 += __shfl_xor_sync(0xffffffffu, l0, 2);
    l1 += __shfl_xor_sync(0xffffffffu, l1, 1);
    l1 += __shfl_xor_sync(0xffffffffu, l1, 2);
    float inv0 = 1.f / l0;
    float inv1 = 1.f / l1;

    float* Og0 = O + ((size_t)b * SEQ + wrow + g) * DIM;
    float* Og1 = Og0 + 8 * DIM;
    #pragma unroll
    for (int dt = 0; dt < 32; dt++) {
        int col = dt * 8 + 2 * t;
        float2 v0 = make_float2(o[dt][0] * inv0, o[dt][1] * inv0);
        float2 v1 = make_float2(o[dt][2] * inv1, o[dt][3] * inv1);
        *reinterpret_cast<float2*>(Og0 + col) = v0;
        *reinterpret_cast<float2*>(Og1 + col) = v1;
    }
}

extern "C" void kernel_launch(void* const* d_in, const int* in_sizes, int n_in,
                              void* d_out, int out_size)
{
    const float* Q  = (const float*)d_in[0];
    const float* K  = (const float*)d_in[1];
    const float* V  = (const float*)d_in[2];
    const int*   PM = (const int*)d_in[3];
    float*       O  = (float*)d_out;

    cudaFuncSetAttribute(fa_tf32_kernel,
                         cudaFuncAttributeMaxDynamicSharedMemorySize, SMEM_BYTES);
    fa_tf32_kernel<<<BATCH * NTQ, NTHR, SMEM_BYTES>>>(Q, K, V, PM, O);
}

// round 8
// speedup vs baseline: 1.1321x; 1.1321x over previous
#include <cuda_runtime.h>
#include <cuda_bf16.h>
#include <cstdint>

// Causal attention, B=16, N=2048, D=256, fp32 I/O.
// FlashAttention-2, tf32 mma.sync (m16n8k8), XOR-swizzled fragment smem (R5 layouts).
// R7: 512-thread CTA; warp pairs (w, w+8) share 16 q-rows and split D
//     -> O accumulator 64 regs/thread, 16 warps/SM (2x latency hiding).

#define BQ    128
#define BK    32
#define NWARP 16
#define NTHR  512
#define BATCH 16
#define SEQ   2048
#define DIM   256
#define NTQ   (SEQ / BQ)
#define QK_SCALE 0.0625f
#define LOG2E 1.4426950408889634f

// smem (uint32 words)
#define QS_OFF   0        // Q A-frags: 8 wrb * 32 c * 128 words        (131072 B)
#define KS_OFF   32768    // K B-frags: 4 nt * 32 c * 64 words          (32768 B)
#define VS_OFF   40960    // V B-frags: 32 dt * 4 kc * 64 words         (32768 B)
#define PS_OFF   49152    // P A-frags: 8 wp * 4 nt * 128 words         (16384 B)
#define PAD_OFF  53248    // 32 ints
#define RM_OFF   53280    // row-max exchange: 2 halves * 128 rows
#define LS_OFF   53536    // l partial exchange: 2 halves * 8 wp * 32 lanes * 2
#define SMEM_WORDS (53536 + 1024)
#define SMEM_BYTES (SMEM_WORDS * 4)

__device__ __forceinline__ uint32_t f2tf32(float x) {
    uint32_t u;
    asm("cvt.rna.tf32.f32 %0, %1;" : "=r"(u) : "f"(x));
    return u;
}

__device__ __forceinline__ float ex2(float x) {
    float r;
    asm("ex2.approx.ftz.f32 %0, %1;" : "=f"(r) : "f"(x));
    return r;
}

__device__ __forceinline__ void mma8(float* d, const uint32_t* a, const uint32_t* b) {
    asm volatile(
        "mma.sync.aligned.m16n8k8.row.col.f32.tf32.tf32.f32 "
        "{%0,%1,%2,%3},{%4,%5,%6,%7},{%8,%9},{%0,%1,%2,%3};\n"
        : "+f"(d[0]), "+f"(d[1]), "+f"(d[2]), "+f"(d[3])
        : "r"(a[0]), "r"(a[1]), "r"(a[2]), "r"(a[3]), "r"(b[0]), "r"(b[1]));
}

__device__ __forceinline__ void pair_bar(int id) {
    asm volatile("bar.sync %0, %1;" :: "r"(id), "r"(64) : "memory");
}

__global__ void __launch_bounds__(NTHR, 1)
fa_tf32_kernel(const float* __restrict__ Q, const float* __restrict__ K,
               const float* __restrict__ V, const int* __restrict__ PM,
               float* __restrict__ O)
{
    extern __shared__ uint32_t sm[];
    uint32_t* Qs = sm + QS_OFF;
    uint32_t* Ks = sm + KS_OFF;
    uint32_t* Vs = sm + VS_OFF;
    uint32_t* Ps = sm + PS_OFF;
    int*   pads  = (int*)(sm + PAD_OFF);
    float* rmex  = (float*)(sm + RM_OFF);
    float* lsex  = (float*)(sm + LS_OFF);

    const int tid  = threadIdx.x;
    const int warp = tid >> 5;
    const int lane = tid & 31;
    const int wp   = warp & 7;     // row-group
    const int half = warp >> 3;    // D-half (0: cols 0..127, 1: cols 128..255)
    const int g    = lane >> 2;
    const int t    = lane & 3;

    const int b  = blockIdx.x & (BATCH - 1);
    const int qt = NTQ - 1 - (blockIdx.x >> 4);
    const int q0 = qt * BQ;

    // ---- stage Q tile (A-fragment layout, pre-scaled, XOR-swizzled) ----
    const float* Qg = Q + ((size_t)b * SEQ + q0) * DIM;
    for (int i = tid; i < BQ * DIM / 4; i += NTHR) {
        int idx = i * 4;
        float4 v = *reinterpret_cast<const float4*>(Qg + idx);
        int r = idx >> 8;
        int d = idx & 255;
        float vv[4] = {v.x, v.y, v.z, v.w};
        #pragma unroll
        for (int e = 0; e < 4; e++) {
            int dd = d + e;
            int wrb   = r >> 4;
            int c     = dd >> 3;
            int lane2 = ((r & 7) << 2) | (dd & 3);
            int a     = ((r >> 3) & 1) | (((dd >> 2) & 1) << 1);
            uint32_t off = (uint32_t)(((lane2 << 2) | a) ^ ((c & 7) << 2));
            Qs[(uint32_t)(wrb * 32 + c) * 128 + off] = f2tf32(vv[e] * QK_SCALE);
        }
    }

    // ---- accumulators: 16 d-tiles (half of D) ----
    float o[16][4];
    #pragma unroll
    for (int i = 0; i < 16; i++) { o[i][0] = 0.f; o[i][1] = 0.f; o[i][2] = 0.f; o[i][3] = 0.f; }
    float m0 = -1e30f, m1 = -1e30f, l0 = 0.f, l1 = 0.f;

    const int wrow = q0 + wp * 16;
    const int KT   = (q0 + BQ) / BK;
    const float* Kg0 = K + (size_t)b * SEQ * DIM;
    const float* Vg0 = V + (size_t)b * SEQ * DIM;

    for (int kt = 0; kt < KT; kt++) {
        const int k0 = kt * BK;

        __syncthreads();
        // ---- stage K,V tiles (XOR-swizzled B-fragment layouts) ----
        const float* Kg = Kg0 + (size_t)k0 * DIM;
        const float* Vg = Vg0 + (size_t)k0 * DIM;
        for (int i = tid; i < BK * DIM / 4; i += NTHR) {
            int idx = i * 4;
            float4 kv = *reinterpret_cast<const float4*>(Kg + idx);
            float4 vv = *reinterpret_cast<const float4*>(Vg + idx);
            int r = idx >> 8;
            int d = idx & 255;
            float ka[4] = {kv.x, kv.y, kv.z, kv.w};
            float va[4] = {vv.x, vv.y, vv.z, vv.w};
            #pragma unroll
            for (int e = 0; e < 4; e++) {
                int dd = d + e;
                {
                    int nt    = r >> 3;
                    int c     = dd >> 3;
                    int lane2 = ((r & 7) << 2) | (dd & 3);
                    int bi    = (dd >> 2) & 1;
                    uint32_t off = (uint32_t)(((lane2 << 1) | bi) ^ ((c & 15) << 1));
                    Ks[(uint32_t)(nt * 32 + c) * 64 + off] = f2tf32(ka[e]);
                }
                {
                    int dt    = dd >> 3;
                    int kc    = r >> 3;
                    int lane2 = ((dd & 7) << 2) | (r & 3);
                    int bi    = (r >> 2) & 1;
                    uint32_t off = (uint32_t)(((lane2 << 1) | bi) ^ ((dt & 15) << 1));
                    Vs[(uint32_t)(dt * 4 + kc) * 64 + off] = f2tf32(va[e]);
                }
            }
        }
        if (tid < BK) pads[tid] = PM[(size_t)b * SEQ + k0 + tid];
        __syncthreads();

        if (k0 > wrow + 15) continue;   // pair-uniform skip (both halves same wrow)

        // ---- S half: this warp computes nt = half*2 + {0,1} ----
        float s[2][4];
        s[0][0]=s[0][1]=s[0][2]=s[0][3]=0.f;
        s[1][0]=s[1][1]=s[1][2]=s[1][3]=0.f;
        #pragma unroll
        for (int c = 0; c < 32; c++) {
            uint32_t qoff = (uint32_t)((lane << 2) ^ ((c & 7) << 2));
            uint4 qa = *reinterpret_cast<const uint4*>(&Qs[(uint32_t)(wp * 32 + c) * 128 + qoff]);
            uint32_t A[4] = {qa.x, qa.y, qa.z, qa.w};
            uint32_t koff = (uint32_t)((lane << 1) ^ ((c & 15) << 1));
            #pragma unroll
            for (int ntl = 0; ntl < 2; ntl++) {
                int nt = half * 2 + ntl;
                uint2 kb = *reinterpret_cast<const uint2*>(&Ks[(uint32_t)(nt * 32 + c) * 64 + koff]);
                uint32_t Bf[2] = {kb.x, kb.y};
                mma8(s[ntl], A, Bf);
            }
        }

        // ---- mask + per-half row max ----
        const int row0 = wrow + g;
        const int row1 = row0 + 8;
        float rm0 = -1e30f, rm1 = -1e30f;
        #pragma unroll
        for (int ntl = 0; ntl < 2; ntl++) {
            int nt = half * 2 + ntl;
            int j0 = k0 + nt * 8 + 2 * t;
            int j1 = j0 + 1;
            bool ok0 = (pads[j0 - k0] != 0);
            bool ok1 = (pads[j1 - k0] != 0);
            if (!(ok0 && j0 <= row0)) s[ntl][0] = -1e30f;
            if (!(ok1 && j1 <= row0)) s[ntl][1] = -1e30f;
            if (!(ok0 && j0 <= row1)) s[ntl][2] = -1e30f;
            if (!(ok1 && j1 <= row1)) s[ntl][3] = -1e30f;
            rm0 = fmaxf(rm0, fmaxf(s[ntl][0], s[ntl][1]));
            rm1 = fmaxf(rm1, fmaxf(s[ntl][2], s[ntl][3]));
        }
        rm0 = fmaxf(rm0, __shfl_xor_sync(0xffffffffu, rm0, 1));
        rm0 = fmaxf(rm0, __shfl_xor_sync(0xffffffffu, rm0, 2));
        rm1 = fmaxf(rm1, __shfl_xor_sync(0xffffffffu, rm1, 1));
        rm1 = fmaxf(rm1, __shfl_xor_sync(0xffffffffu, rm1, 2));

        // ---- cross-half max exchange ----
        rmex[half * 128 + wp * 16 + g]     = rm0;
        rmex[half * 128 + wp * 16 + 8 + g] = rm1;
        pair_bar(wp + 1);
        rm0 = fmaxf(rm0, rmex[(1 - half) * 128 + wp * 16 + g]);
        rm1 = fmaxf(rm1, rmex[(1 - half) * 128 + wp * 16 + 8 + g]);

        float mn0 = fmaxf(m0, rm0), mn1 = fmaxf(m1, rm1);
        float sc0 = ex2((m0 - mn0) * LOG2E);
        float sc1 = ex2((m1 - mn1) * LOG2E);
        m0 = mn0; m1 = mn1;
        l0 *= sc0; l1 *= sc1;
        #pragma unroll
        for (int dt = 0; dt < 16; dt++) {
            o[dt][0] *= sc0; o[dt][1] *= sc0;
            o[dt][2] *= sc1; o[dt][3] *= sc1;
        }

        // ---- p, P fragment write (this half's nt pair), partial l ----
        float ls0 = 0.f, ls1 = 0.f;
        #pragma unroll
        for (int ntl = 0; ntl < 2; ntl++) {
            int nt = half * 2 + ntl;
            float p0 = ex2((s[ntl][0] - mn0) * LOG2E);
            float p1 = ex2((s[ntl][1] - mn0) * LOG2E);
            float p2 = ex2((s[ntl][2] - mn1) * LOG2E);
            float p3 = ex2((s[ntl][3] - mn1) * LOG2E);
            ls0 += p0 + p1;
            ls1 += p2 + p3;
            int base = (wp * 4 + nt) * 128;
            int t20 = (2 * t) & 3,     hi0 = (2 * t) >> 2;
            int t21 = (2 * t + 1) & 3, hi1 = (2 * t + 1) >> 2;
            Ps[base + (g * 4 + t20) * 4 + 0 + 2 * hi0] = f2tf32(p0);
            Ps[base + (g * 4 + t21) * 4 + 0 + 2 * hi1] = f2tf32(p1);
            Ps[base + (g * 4 + t20) * 4 + 1 + 2 * hi0] = f2tf32(p2);
            Ps[base + (g * 4 + t21) * 4 + 1 + 2 * hi1] = f2tf32(p3);
        }
        lsex[(half * 8 + wp) * 64 + lane * 2]     = ls0;
        lsex[(half * 8 + wp) * 64 + lane * 2 + 1] = ls1;
        pair_bar(wp + 1);   // orders P writes + ls exchange for both halves
        l0 += ls0 + lsex[((1 - half) * 8 + wp) * 64 + lane * 2];
        l1 += ls1 + lsex[((1 - half) * 8 + wp) * 64 + lane * 2 + 1];

        // ---- O half += P V : full P (4 kc), this half's 16 d-tiles ----
        #pragma unroll
        for (int kc = 0; kc < 4; kc++) {
            uint4 pa = *reinterpret_cast<const uint4*>(&Ps[(wp * 4 + kc) * 128 + lane * 4]);
            uint32_t A[4] = {pa.x, pa.y, pa.z, pa.w};
            #pragma unroll
            for (int dtl = 0; dtl < 16; dtl++) {
                int dt = half * 16 + dtl;
                uint32_t voff = (uint32_t)((lane << 1) ^ ((dt & 15) << 1));
                uint2 vb = *reinterpret_cast<const uint2*>(&Vs[(uint32_t)(dt * 4 + kc) * 64 + voff]);
                uint32_t Bf[2] = {vb.x, vb.y};
                mma8(o[dtl], A, Bf);
            }
        }
    }

    // ---- epilogue ----
    l0 += __shfl_xor_sync(0xffffffffu, l0, 1);
    l0 += __shfl_xor_sync(0xffffffffu, l0, 2);
    l1 += __shfl_xor_sync(0xffffffffu, l1, 1);
    l1 += __shfl_xor_sync(0xffffffffu, l1, 2);
    float inv0 = 1.f / l0;
    float inv1 = 1.f / l1;

    float* Og0 = O + ((size_t)b * SEQ + wrow + g) * DIM + half * 128;
    float* Og1 = Og0 + 8 * DIM;
    #pragma unroll
    for (int dtl = 0; dtl < 16; dtl++) {
        int col = dtl * 8 + 2 * t;
        float2 v0 = make_float2(o[dtl][0] * inv0, o[dtl][1] * inv0);
        float2 v1 = make_float2(o[dtl][2] * inv1, o[dtl][3] * inv1);
        *reinterpret_cast<float2*>(Og0 + col) = v0;
        *reinterpret_cast<float2*>(Og1 + col) = v1;
    }
}

extern "C" void kernel_launch(void* const* d_in, const int* in_sizes, int n_in,
                              void* d_out, int out_size)
{
    const float* Q  = (const float*)d_in[0];
    const float* K  = (const float*)d_in[1];
    const float* V  = (const float*)d_in[2];
    const int*   PM = (const int*)d_in[3];
    float*       O  = (float*)d_out;

    cudaFuncSetAttribute(fa_tf32_kernel,
                         cudaFuncAttributeMaxDynamicSharedMemorySize, SMEM_BYTES);
    fa_tf32_kernel<<<BATCH * NTQ, NTHR, SMEM_BYTES>>>(Q, K, V, PM, O);
}